// round 15
// baseline (speedup 1.0000x reference)
#include <cuda_runtime.h>
#include <cuda_fp16.h>
#include <cstdint>
#include <cstddef>

// Problem constants
#define B_  16
#define S_  512
#define D_  1024
#define H_  16
#define DH_ 64
#define M_  (B_ * S_)   // 8192

// Q pre-scale: 1/sqrt(64) * log2(e) — folded into Q projection epilogue
#define QSCALE 0.18033688011112042f

// ---------------------------------------------------------------------------
// Scratch (static device globals), all single fp16
// ---------------------------------------------------------------------------
__device__ __align__(128) __half g_X[M_ * D_];      // v (fp16), later attn out (row-major)
__device__ __align__(128) __half g_B[4 * D_ * D_];  // concat W^T [4096][1024] (Q,K,V,O)
__device__ __align__(128) __half g_Q[M_ * D_];      // head-major [b,h,s,dh]
__device__ __align__(128) __half g_K[M_ * D_];
__device__ __align__(128) __half g_V[M_ * D_];

// ---------------------------------------------------------------------------
// PTX helpers (sm_80+ only; compute_103 lowering rejects sm_103a-only features)
// ---------------------------------------------------------------------------
__device__ __forceinline__ uint32_t smem_u32(const void* p) {
    uint32_t a;
    asm("{ .reg .u64 t; cvta.to.shared.u64 t, %1; cvt.u32.u64 %0, t; }" : "=r"(a) : "l"(p));
    return a;
}
__device__ __forceinline__ void cp16(uint32_t saddr, const void* gaddr) {
    asm volatile("cp.async.cg.shared.global [%0], [%1], 16;" :: "r"(saddr), "l"(gaddr) : "memory");
}
#define CP_COMMIT() asm volatile("cp.async.commit_group;" ::: "memory")
#define CP_WAIT0()  asm volatile("cp.async.wait_group 0;" ::: "memory")
#define CP_WAIT1()  asm volatile("cp.async.wait_group 1;" ::: "memory")

__device__ __forceinline__ void ldsm4(uint32_t* r, uint32_t a) {
    asm volatile("ldmatrix.sync.aligned.m8n8.x4.shared.b16 {%0,%1,%2,%3}, [%4];"
                 : "=r"(r[0]), "=r"(r[1]), "=r"(r[2]), "=r"(r[3]) : "r"(a));
}
__device__ __forceinline__ void ldsm4t(uint32_t* r, uint32_t a) {
    asm volatile("ldmatrix.sync.aligned.m8n8.x4.trans.shared.b16 {%0,%1,%2,%3}, [%4];"
                 : "=r"(r[0]), "=r"(r[1]), "=r"(r[2]), "=r"(r[3]) : "r"(a));
}
// fp16 HMMA, fp32 accumulate
__device__ __forceinline__ void mma16816(float* c, const uint32_t* a, const uint32_t* b) {
    asm volatile(
        "mma.sync.aligned.m16n8k16.row.col.f32.f16.f16.f32 "
        "{%0,%1,%2,%3}, {%4,%5,%6,%7}, {%8,%9}, {%0,%1,%2,%3};"
        : "+f"(c[0]), "+f"(c[1]), "+f"(c[2]), "+f"(c[3])
        : "r"(a[0]), "r"(a[1]), "r"(a[2]), "r"(a[3]), "r"(b[0]), "r"(b[1]));
}
__device__ __forceinline__ float ex2(float x) {
    float r;
    asm("ex2.approx.f32 %0, %1;" : "=f"(r) : "f"(x));
    return r;
}

#define SMEM_SWZ(o)   ((o) ^ (((o) >> 3) & 0x70))   // 128B rows

// ---------------------------------------------------------------------------
// GEMM: C = A @ B^T (+bias), single fp16, fp32 accum.
// CTA tile 128x128, BK=64, 3-stage cp.async, 8 warps 2x4, 2 CTAs/SM.
// ONE barrier per K-iteration: prefetch issued AFTER compute; with 3 stages
// the stage written (c+2)%3 never aliases a stage readable in this segment.
// ---------------------------------------------------------------------------
#define T_A 0
#define T_B 16384
#define STAGE_BYTES 32768
#define GEMM_SMEM (3 * STAGE_BYTES)   // 98304

__device__ __forceinline__ void load_tile64(uint32_t sdst, const __half* g,
                                            int row0, int kc, int tid) {
#pragma unroll
    for (int i = 0; i < 4; i++) {
        int idx = tid + i * 256;          // 1024 transfers of 16B
        int r = idx >> 3, c = idx & 7;    // 128 rows x 8 chunks
        const __half* gp = g + (size_t)(row0 + r) * D_ + kc * 64 + c * 8;
        cp16(sdst + SMEM_SWZ(r * 128 + c * 16), gp);
    }
}

__device__ __forceinline__ void gemm_mainloop(
    uint32_t sb, const __half* A, const __half* Bp,
    int m0, int tid, int wid, int lane, float acc[4][4][4])
{
    const int wm = (wid >> 2) * 64;
    const int wn = (wid & 3) * 32;
    const int a_row = wm + (lane & 15);
    const int a_coff = (lane >> 4) * 16;
    const int b_row = wn + ((lane >> 4) << 3) + (lane & 7);
    const int b_coff = ((lane >> 3) & 1) * 16;

#pragma unroll
    for (int p = 0; p < 2; p++) {
        uint32_t so = sb + p * STAGE_BYTES;
        load_tile64(so + T_A, A, m0, p, tid);
        load_tile64(so + T_B, Bp, 0, p, tid);
        CP_COMMIT();
    }

    int stage = 0, nstage = 2;
#pragma unroll 1
    for (int c = 0; c < 16; c++) {
        if (c < 15) { CP_WAIT1(); } else { CP_WAIT0(); }
        __syncthreads();

        const uint32_t so = sb + stage * STAGE_BYTES;
#pragma unroll
        for (int ks = 0; ks < 4; ks++) {
            const int kb = ks * 32;
            uint32_t ah[4][4], bh[2][4];
#pragma unroll
            for (int mt = 0; mt < 4; mt++) {
                uint32_t off = SMEM_SWZ((a_row + mt * 16) * 128 + kb + a_coff);
                ldsm4(ah[mt], so + T_A + off);
            }
#pragma unroll
            for (int nt2 = 0; nt2 < 2; nt2++) {
                uint32_t off = SMEM_SWZ((b_row + nt2 * 16) * 128 + kb + b_coff);
                ldsm4(bh[nt2], so + T_B + off);
            }
#pragma unroll
            for (int mt = 0; mt < 4; mt++)
#pragma unroll
                for (int nt = 0; nt < 4; nt++)
                    mma16816(acc[mt][nt], ah[mt], &bh[nt >> 1][(nt & 1) * 2]);
        }

        if (c + 2 < 16) {
            uint32_t so2 = sb + nstage * STAGE_BYTES;
            load_tile64(so2 + T_A, A, m0, c + 2, tid);
            load_tile64(so2 + T_B, Bp, 0, c + 2, tid);
            CP_COMMIT();
        }
        stage = (stage + 1) == 3 ? 0 : stage + 1;
        nstage = (nstage + 1) == 3 ? 0 : nstage + 1;
    }
}

// ---------------------------------------------------------------------------
// Fused QKV projection GEMM: grid (24, 64); proj = n0>>10. K/V skip by length.
// Q output pre-scaled by QSCALE. All outputs fp16 head-major [b,h,s,dh].
// ---------------------------------------------------------------------------
__global__ __launch_bounds__(256, 2) void gemm_qkv(
    const __half* __restrict__ A, const __half* __restrict__ Bc,
    const float* __restrict__ bq, const float* __restrict__ bk, const float* __restrict__ bv,
    __half* __restrict__ qo, __half* __restrict__ ko, __half* __restrict__ vo,
    const int* __restrict__ lengths)
{
    extern __shared__ __align__(1024) char smem[];
    const int tid  = threadIdx.x;
    const int wid  = tid >> 5, lane = tid & 31;
    const int m0   = blockIdx.y * 128;
    const int n0   = blockIdx.x * 128;
    const int proj = n0 >> 10;

    if (proj != 0) {
        int len = lengths[m0 >> 9];
        if ((m0 & 511) >= ((len + 63) & ~63)) return;
    }

    const float* bias = (proj == 0) ? bq : (proj == 1) ? bk : bv;
    __half* Co = (proj == 0) ? qo : (proj == 1) ? ko : vo;
    const float sc = (proj == 0) ? QSCALE : 1.0f;

    uint32_t sb = smem_u32(smem);
    float acc[4][4][4];
#pragma unroll
    for (int i = 0; i < 4; i++)
#pragma unroll
        for (int j = 0; j < 4; j++)
#pragma unroll
            for (int k = 0; k < 4; k++) acc[i][j][k] = 0.f;

    gemm_mainloop(sb, A, Bc + (size_t)n0 * D_, m0, tid, wid, lane, acc);

    const int wm = (wid >> 2) * 64;
    const int wn = (wid & 3) * 32;
    const int er = lane >> 2;
    const int ec = (lane & 3) * 2;
#pragma unroll
    for (int mt = 0; mt < 4; mt++) {
#pragma unroll
        for (int nt = 0; nt < 4; nt++) {
            int row = m0 + wm + mt * 16 + er;
            int lc  = (n0 & 1023) + wn + nt * 8 + ec;
            float b0 = bias[lc], b1 = bias[lc + 1];
            int bb = row >> 9, ss = row & 511, hh = lc >> 6, dd = lc & 63;
            size_t base = (((size_t)bb * H_ + hh) * S_ + ss) * DH_ + dd;
            *(__half2*)(Co + base) =
                __floats2half2_rn((acc[mt][nt][0] + b0) * sc, (acc[mt][nt][1] + b1) * sc);
            *(__half2*)(Co + base + 8 * DH_) =
                __floats2half2_rn((acc[mt][nt][2] + b0) * sc, (acc[mt][nt][3] + b1) * sc);
        }
    }
}

// ---------------------------------------------------------------------------
// Output projection GEMM: out = A @ Wo^T + bo (fp32 row-major), grid (8, 64)
// ---------------------------------------------------------------------------
__global__ __launch_bounds__(256, 2) void gemm_out(
    const __half* __restrict__ A, const __half* __restrict__ Bc,
    const float* __restrict__ bias, float* __restrict__ C)
{
    extern __shared__ __align__(1024) char smem[];
    const int tid  = threadIdx.x;
    const int wid  = tid >> 5, lane = tid & 31;
    const int m0   = blockIdx.y * 128;
    const int n0   = blockIdx.x * 128;

    uint32_t sb = smem_u32(smem);
    float acc[4][4][4];
#pragma unroll
    for (int i = 0; i < 4; i++)
#pragma unroll
        for (int j = 0; j < 4; j++)
#pragma unroll
            for (int k = 0; k < 4; k++) acc[i][j][k] = 0.f;

    gemm_mainloop(sb, A, Bc + (size_t)n0 * D_, m0, tid, wid, lane, acc);

    const int wm = (wid >> 2) * 64;
    const int wn = (wid & 3) * 32;
    const int er = lane >> 2;
    const int ec = (lane & 3) * 2;
#pragma unroll
    for (int mt = 0; mt < 4; mt++) {
#pragma unroll
        for (int nt = 0; nt < 4; nt++) {
            int row = m0 + wm + mt * 16 + er;
            int col = n0 + wn + nt * 8 + ec;
            float b0 = bias[col], b1 = bias[col + 1];
            float2 p0 = make_float2(acc[mt][nt][0] + b0, acc[mt][nt][1] + b1);
            float2 p1 = make_float2(acc[mt][nt][2] + b0, acc[mt][nt][3] + b1);
            *(float2*)(C + (size_t)row * D_ + col) = p0;
            *(float2*)(C + (size_t)(row + 8) * D_ + col) = p1;
        }
    }
}

// ---------------------------------------------------------------------------
// HMMA flash attention, fp16 operands, fp32 accum, exp2-domain softmax.
// l kept as per-thread partial (f rescale is quad-uniform); quad-reduced once
// in the epilogue — removes 4 SHFL per tile from the critical scalar path.
// ---------------------------------------------------------------------------
#define AQ   0
#define AST  16384
#define AK   0
#define AV   8192
#define AST_BYTES 16384
#define ATTN_SMEM (16384 + 2 * AST_BYTES)   // 49152

__global__ __launch_bounds__(256, 2) void attn_mma(
    const __half* __restrict__ Q_, const __half* __restrict__ K_,
    const __half* __restrict__ V_, const int* __restrict__ lengths,
    __half* __restrict__ O_)
{
    extern __shared__ __align__(1024) char smem[];
    const int tid = threadIdx.x, wid = tid >> 5, lane = tid & 31;
    const int b = blockIdx.z, h = blockIdx.y, q0 = blockIdx.x * 128;
    const int len = lengths[b];
    uint32_t sb = smem_u32(smem);
    const size_t bh_off = ((size_t)b * H_ + h) * (S_ * DH_);

    // Q tile load (128 rows x 128B)
#pragma unroll
    for (int i = 0; i < 4; i++) {
        int idx = tid + i * 256;
        int r = idx >> 3, c = idx & 7;
        cp16(sb + AQ + SMEM_SWZ(r * 128 + c * 16), Q_ + bh_off + (size_t)(q0 + r) * DH_ + c * 8);
    }
    CP_COMMIT();

    const int jend = (len + 63) & ~63;
    const int ntile = jend >> 6;

    // prefetch KV tile 0 -> stage 0
    {
        uint32_t so = sb + AST;
#pragma unroll
        for (int i = 0; i < 2; i++) {
            int idx = tid + i * 256;
            int r = idx >> 3, c = idx & 7;
            size_t g = bh_off + (size_t)r * DH_ + c * 8;
            uint32_t sw = SMEM_SWZ(r * 128 + c * 16);
            cp16(so + AK + sw, K_ + g);
            cp16(so + AV + sw, V_ + g);
        }
        CP_COMMIT();
    }

    CP_WAIT1();
    __syncthreads();

    const int a_row = wid * 16 + (lane & 15);
    const int a_co = (lane >> 4) * 16;
    uint32_t qh[4][4];
#pragma unroll
    for (int s = 0; s < 4; s++) {
        uint32_t off = SMEM_SWZ(a_row * 128 + s * 32 + a_co);
        ldsm4(qh[s], sb + AQ + off);
    }

    float oa[8][4];
#pragma unroll
    for (int i = 0; i < 8; i++)
#pragma unroll
        for (int j = 0; j < 4; j++) oa[i][j] = 0.f;
    float m0 = -1e30f, m1 = -1e30f, l0 = 0.f, l1 = 0.f;   // l = per-thread partial

    const int krow = ((lane >> 4) << 3) + (lane & 7);
    const int kco  = ((lane >> 3) & 1) * 16;
    const int vrow = lane & 15;
    const int vco  = (lane >> 4) * 16;

#pragma unroll 1
    for (int t = 0; t < ntile; t++) {
        CP_WAIT0();
        __syncthreads();
        if (t + 1 < ntile) {
            uint32_t so = sb + AST + ((t + 1) & 1) * AST_BYTES;
            int j0n = (t + 1) * 64;
#pragma unroll
            for (int i = 0; i < 2; i++) {
                int idx = tid + i * 256;
                int r = idx >> 3, c = idx & 7;
                size_t g = bh_off + (size_t)(j0n + r) * DH_ + c * 8;
                uint32_t sw = SMEM_SWZ(r * 128 + c * 16);
                cp16(so + AK + sw, K_ + g);
                cp16(so + AV + sw, V_ + g);
            }
            CP_COMMIT();
        }

        const uint32_t so = sb + AST + (t & 1) * AST_BYTES;
        const int j0 = t * 64;

        // ---- S = Q @ K^T (log2 domain via Q pre-scale) ----
        float S[8][4];
#pragma unroll
        for (int i = 0; i < 8; i++)
#pragma unroll
            for (int j = 0; j < 4; j++) S[i][j] = 0.f;
#pragma unroll
        for (int s = 0; s < 4; s++) {
            uint32_t kh4[4][4];
#pragma unroll
            for (int g = 0; g < 4; g++) {
                uint32_t off = SMEM_SWZ((g * 16 + krow) * 128 + s * 32 + kco);
                ldsm4(kh4[g], so + AK + off);
            }
#pragma unroll
            for (int g = 0; g < 4; g++) {
                mma16816(S[2 * g],     qh[s], kh4[g]);
                mma16816(S[2 * g + 1], qh[s], kh4[g] + 2);
            }
        }

        // ---- mask (partial tiles only) ----
        if (j0 + 64 > len) {
            int kb0 = j0 + 2 * (lane & 3);
#pragma unroll
            for (int j = 0; j < 8; j++) {
#pragma unroll
                for (int e = 0; e < 4; e++) {
                    int kk = kb0 + 8 * j + (e & 1);
                    if (kk >= len) S[j][e] = -1e9f;
                }
            }
        }

        // ---- online softmax (base-2; row max shared via quad shuffles) ----
        float mx0 = -1e30f, mx1 = -1e30f;
#pragma unroll
        for (int j = 0; j < 8; j++) {
            mx0 = fmaxf(mx0, fmaxf(S[j][0], S[j][1]));
            mx1 = fmaxf(mx1, fmaxf(S[j][2], S[j][3]));
        }
        mx0 = fmaxf(mx0, __shfl_xor_sync(0xffffffffu, mx0, 1));
        mx0 = fmaxf(mx0, __shfl_xor_sync(0xffffffffu, mx0, 2));
        mx1 = fmaxf(mx1, __shfl_xor_sync(0xffffffffu, mx1, 1));
        mx1 = fmaxf(mx1, __shfl_xor_sync(0xffffffffu, mx1, 2));
        float mn0 = fmaxf(m0, mx0), mn1 = fmaxf(m1, mx1);
        float f0 = ex2(m0 - mn0), f1 = ex2(m1 - mn1);
        l0 *= f0; l1 *= f1;
#pragma unroll
        for (int i = 0; i < 8; i++) {
            oa[i][0] *= f0; oa[i][1] *= f0; oa[i][2] *= f1; oa[i][3] *= f1;
        }
#pragma unroll
        for (int j = 0; j < 8; j++) {
            S[j][0] = ex2(S[j][0] - mn0);
            S[j][1] = ex2(S[j][1] - mn0);
            S[j][2] = ex2(S[j][2] - mn1);
            S[j][3] = ex2(S[j][3] - mn1);
            l0 += S[j][0] + S[j][1];
            l1 += S[j][2] + S[j][3];
        }
        m0 = mn0; m1 = mn1;

        // ---- O += P @ V ----
#pragma unroll
        for (int s = 0; s < 4; s++) {
            uint32_t pah[4];
#pragma unroll
            for (int half = 0; half < 2; half++) {
                const float* Sf = S[2 * s + half];
                __half2 hp0 = __floats2half2_rn(Sf[0], Sf[1]);
                __half2 hp1 = __floats2half2_rn(Sf[2], Sf[3]);
                pah[2 * half]     = *(uint32_t*)&hp0;
                pah[2 * half + 1] = *(uint32_t*)&hp1;
            }
            uint32_t vh4[4][4];
#pragma unroll
            for (int g = 0; g < 4; g++) {
                uint32_t off = SMEM_SWZ((s * 16 + vrow) * 128 + g * 32 + vco);
                ldsm4t(vh4[g], so + AV + off);
            }
#pragma unroll
            for (int g = 0; g < 4; g++) {
                mma16816(oa[2 * g],     pah, vh4[g]);
                mma16816(oa[2 * g + 1], pah, vh4[g] + 2);
            }
        }
    }

    // ---- epilogue: quad-reduce l, normalize, write fp16 row-major [M][D] ----
    l0 += __shfl_xor_sync(0xffffffffu, l0, 1);
    l0 += __shfl_xor_sync(0xffffffffu, l0, 2);
    l1 += __shfl_xor_sync(0xffffffffu, l1, 1);
    l1 += __shfl_xor_sync(0xffffffffu, l1, 2);
    float il0 = 1.f / l0, il1 = 1.f / l1;
    int qrow = q0 + wid * 16 + (lane >> 2);
    size_t base0 = ((size_t)b * S_ + qrow) * D_ + h * DH_ + 2 * (lane & 3);
    size_t base1 = base0 + (size_t)8 * D_;
#pragma unroll
    for (int nf = 0; nf < 8; nf++) {
        *(__half2*)(O_ + base0 + 8 * nf) = __floats2half2_rn(oa[nf][0] * il0, oa[nf][1] * il0);
        *(__half2*)(O_ + base1 + 8 * nf) = __floats2half2_rn(oa[nf][2] * il1, oa[nf][3] * il1);
    }
}

// ---------------------------------------------------------------------------
// Combined prep: z 0..3 = weight transpose, z 4..11 = v fp32->fp16.
// grid (32,32,12), block (32,8).
// ---------------------------------------------------------------------------
__global__ __launch_bounds__(256) void prep_kernel(
    const float* __restrict__ W0, const float* __restrict__ W1,
    const float* __restrict__ W2, const float* __restrict__ W3,
    __half* __restrict__ T_,
    const float4* __restrict__ x, __half2* __restrict__ xo)
{
    const int z = blockIdx.z;
    if (z < 4) {
        __shared__ float t[32][33];
        const float* W = (z == 0) ? W0 : (z == 1) ? W1 : (z == 2) ? W2 : W3;
        const int n0 = blockIdx.x * 32, k0 = blockIdx.y * 32;
        const int tx = threadIdx.x, ty = threadIdx.y;
#pragma unroll
        for (int i = 0; i < 4; i++)
            t[ty + i * 8][tx] = W[(size_t)(k0 + ty + i * 8) * D_ + n0 + tx];
        __syncthreads();
#pragma unroll
        for (int i = 0; i < 4; i++) {
            int n = z * D_ + n0 + ty + i * 8;
            T_[(size_t)n * D_ + k0 + tx] = __float2half_rn(t[tx][ty + i * 8]);
        }
    } else {
        int tid = threadIdx.y * 32 + threadIdx.x;
        int blk = (z - 4) * 1024 + blockIdx.y * 32 + blockIdx.x;
        int i = blk * 256 + tid;
        float4 v = x[i];
        xo[2 * i]     = __floats2half2_rn(v.x, v.y);
        xo[2 * i + 1] = __floats2half2_rn(v.z, v.w);
    }
}

// ---------------------------------------------------------------------------
// Launch
// ---------------------------------------------------------------------------
extern "C" void kernel_launch(void* const* d_in, const int* in_sizes, int n_in,
                              void* d_out, int out_size)
{
    (void)in_sizes; (void)n_in; (void)out_size;
    const float* v       = (const float*)d_in[0];
    const int*   lengths = (const int*)  d_in[1];
    const float* Wq      = (const float*)d_in[2];
    const float* bq      = (const float*)d_in[3];
    const float* Wk      = (const float*)d_in[4];
    const float* bk      = (const float*)d_in[5];
    const float* Wv      = (const float*)d_in[6];
    const float* bv      = (const float*)d_in[7];
    const float* Wo      = (const float*)d_in[8];
    const float* bo      = (const float*)d_in[9];
    float* out = (float*)d_out;

    __half *xb, *wb, *qb, *kb, *vb;
    cudaGetSymbolAddress((void**)&xb, g_X);
    cudaGetSymbolAddress((void**)&wb, g_B);
    cudaGetSymbolAddress((void**)&qb, g_Q);
    cudaGetSymbolAddress((void**)&kb, g_K);
    cudaGetSymbolAddress((void**)&vb, g_V);

    cudaFuncSetAttribute(gemm_qkv, cudaFuncAttributeMaxDynamicSharedMemorySize, GEMM_SMEM);
    cudaFuncSetAttribute(gemm_out, cudaFuncAttributeMaxDynamicSharedMemorySize, GEMM_SMEM);
    cudaFuncSetAttribute(attn_mma, cudaFuncAttributeMaxDynamicSharedMemorySize, ATTN_SMEM);

    dim3 gprep(32, 32, 12), bprep(32, 8);
    prep_kernel<<<gprep, bprep>>>(Wq, Wk, Wv, Wo, wb, (const float4*)v, (__half2*)xb);

    dim3 gqkv(3 * D_ / 128, M_ / 128);   // (24, 64)
    gemm_qkv<<<gqkv, 256, GEMM_SMEM>>>(xb, wb, bq, bk, bv, qb, kb, vb, lengths);

    dim3 ga(S_ / 128, H_, B_);           // (4, 16, 16)
    attn_mma<<<ga, 256, ATTN_SMEM>>>(qb, kb, vb, lengths, xb);

    dim3 go(D_ / 128, M_ / 128);         // (8, 64)
    gemm_out<<<go, 256, GEMM_SMEM>>>(xb, wb + (size_t)3 * D_ * D_, bo, out);
}

// round 16
// speedup vs baseline: 1.0242x; 1.0242x over previous
#include <cuda_runtime.h>
#include <cuda_fp16.h>
#include <cstdint>
#include <cstddef>

// Problem constants
#define B_  16
#define S_  512
#define D_  1024
#define H_  16
#define DH_ 64
#define M_  (B_ * S_)   // 8192

// Q pre-scale: 1/sqrt(64) * log2(e) — folded into Q projection epilogue
#define QSCALE 0.18033688011112042f

// ---------------------------------------------------------------------------
// Scratch (static device globals), all single fp16
// ---------------------------------------------------------------------------
__device__ __align__(128) __half g_X[M_ * D_];      // v (fp16), later attn out (row-major)
__device__ __align__(128) __half g_B[4 * D_ * D_];  // concat W^T [4096][1024] (Q,K,V,O)
__device__ __align__(128) __half g_Q[M_ * D_];      // head-major [b,h,s,dh]
__device__ __align__(128) __half g_K[M_ * D_];
__device__ __align__(128) __half g_V[M_ * D_];

// ---------------------------------------------------------------------------
// PTX helpers (sm_80+ only; compute_103 lowering rejects sm_103a-only features)
// ---------------------------------------------------------------------------
__device__ __forceinline__ uint32_t smem_u32(const void* p) {
    uint32_t a;
    asm("{ .reg .u64 t; cvta.to.shared.u64 t, %1; cvt.u32.u64 %0, t; }" : "=r"(a) : "l"(p));
    return a;
}
__device__ __forceinline__ void cp16(uint32_t saddr, const void* gaddr) {
    asm volatile("cp.async.cg.shared.global [%0], [%1], 16;" :: "r"(saddr), "l"(gaddr) : "memory");
}
#define CP_COMMIT() asm volatile("cp.async.commit_group;" ::: "memory")
#define CP_WAIT0()  asm volatile("cp.async.wait_group 0;" ::: "memory")
#define CP_WAIT1()  asm volatile("cp.async.wait_group 1;" ::: "memory")
#define CP_WAIT2()  asm volatile("cp.async.wait_group 2;" ::: "memory")

__device__ __forceinline__ void ldsm4(uint32_t* r, uint32_t a) {
    asm volatile("ldmatrix.sync.aligned.m8n8.x4.shared.b16 {%0,%1,%2,%3}, [%4];"
                 : "=r"(r[0]), "=r"(r[1]), "=r"(r[2]), "=r"(r[3]) : "r"(a));
}
__device__ __forceinline__ void ldsm4t(uint32_t* r, uint32_t a) {
    asm volatile("ldmatrix.sync.aligned.m8n8.x4.trans.shared.b16 {%0,%1,%2,%3}, [%4];"
                 : "=r"(r[0]), "=r"(r[1]), "=r"(r[2]), "=r"(r[3]) : "r"(a));
}
// fp16 HMMA, fp32 accumulate
__device__ __forceinline__ void mma16816(float* c, const uint32_t* a, const uint32_t* b) {
    asm volatile(
        "mma.sync.aligned.m16n8k16.row.col.f32.f16.f16.f32 "
        "{%0,%1,%2,%3}, {%4,%5,%6,%7}, {%8,%9}, {%0,%1,%2,%3};"
        : "+f"(c[0]), "+f"(c[1]), "+f"(c[2]), "+f"(c[3])
        : "r"(a[0]), "r"(a[1]), "r"(a[2]), "r"(a[3]), "r"(b[0]), "r"(b[1]));
}
__device__ __forceinline__ float ex2(float x) {
    float r;
    asm("ex2.approx.f32 %0, %1;" : "=f"(r) : "f"(x));
    return r;
}

#define SMEM_SWZ(o)   ((o) ^ (((o) >> 3) & 0x70))   // 128B rows

// ---------------------------------------------------------------------------
// GEMM: C = A @ B^T (+bias), single fp16, fp32 accum.
// CTA tile 128x128, BK=64, 3-stage cp.async (prefetch-first, R14 form),
// 8 warps 2x4, 2 CTAs/SM.
// ---------------------------------------------------------------------------
#define T_A 0
#define T_B 16384
#define STAGE_BYTES 32768
#define GEMM_SMEM (3 * STAGE_BYTES)   // 98304

__device__ __forceinline__ void load_tile64(uint32_t sdst, const __half* g,
                                            int row0, int kc, int tid) {
#pragma unroll
    for (int i = 0; i < 4; i++) {
        int idx = tid + i * 256;          // 1024 transfers of 16B
        int r = idx >> 3, c = idx & 7;    // 128 rows x 8 chunks
        const __half* gp = g + (size_t)(row0 + r) * D_ + kc * 64 + c * 8;
        cp16(sdst + SMEM_SWZ(r * 128 + c * 16), gp);
    }
}

__device__ __forceinline__ void gemm_mainloop(
    uint32_t sb, const __half* A, const __half* Bp,
    int m0, int tid, int wid, int lane, float acc[4][4][4])
{
    const int wm = (wid >> 2) * 64;
    const int wn = (wid & 3) * 32;
    const int a_row = wm + (lane & 15);
    const int a_coff = (lane >> 4) * 16;
    const int b_row = wn + ((lane >> 4) << 3) + (lane & 7);
    const int b_coff = ((lane >> 3) & 1) * 16;

#pragma unroll
    for (int p = 0; p < 2; p++) {
        uint32_t so = sb + p * STAGE_BYTES;
        load_tile64(so + T_A, A, m0, p, tid);
        load_tile64(so + T_B, Bp, 0, p, tid);
        CP_COMMIT();
    }

    int stage = 0, nstage = 2;
#pragma unroll 1
    for (int c = 0; c < 16; c++) {
        if (c + 2 < 16) {
            uint32_t so = sb + nstage * STAGE_BYTES;
            load_tile64(so + T_A, A, m0, c + 2, tid);
            load_tile64(so + T_B, Bp, 0, c + 2, tid);
            CP_COMMIT();
            CP_WAIT2();
        } else if (c + 1 < 16) {
            CP_WAIT1();
        } else {
            CP_WAIT0();
        }
        __syncthreads();

        const uint32_t so = sb + stage * STAGE_BYTES;
#pragma unroll
        for (int ks = 0; ks < 4; ks++) {
            const int kb = ks * 32;
            uint32_t ah[4][4], bh[2][4];
#pragma unroll
            for (int mt = 0; mt < 4; mt++) {
                uint32_t off = SMEM_SWZ((a_row + mt * 16) * 128 + kb + a_coff);
                ldsm4(ah[mt], so + T_A + off);
            }
#pragma unroll
            for (int nt2 = 0; nt2 < 2; nt2++) {
                uint32_t off = SMEM_SWZ((b_row + nt2 * 16) * 128 + kb + b_coff);
                ldsm4(bh[nt2], so + T_B + off);
            }
#pragma unroll
            for (int mt = 0; mt < 4; mt++)
#pragma unroll
                for (int nt = 0; nt < 4; nt++)
                    mma16816(acc[mt][nt], ah[mt], &bh[nt >> 1][(nt & 1) * 2]);
        }
        __syncthreads();
        stage = (stage + 1) == 3 ? 0 : stage + 1;
        nstage = (nstage + 1) == 3 ? 0 : nstage + 1;
    }
}

// ---------------------------------------------------------------------------
// Fused QKV projection GEMM: grid (24, 64); proj = n0>>10. K/V skip by length.
// Q output pre-scaled by QSCALE. All outputs fp16 head-major [b,h,s,dh].
// ---------------------------------------------------------------------------
__global__ __launch_bounds__(256, 2) void gemm_qkv(
    const __half* __restrict__ A, const __half* __restrict__ Bc,
    const float* __restrict__ bq, const float* __restrict__ bk, const float* __restrict__ bv,
    __half* __restrict__ qo, __half* __restrict__ ko, __half* __restrict__ vo,
    const int* __restrict__ lengths)
{
    extern __shared__ __align__(1024) char smem[];
    const int tid  = threadIdx.x;
    const int wid  = tid >> 5, lane = tid & 31;
    const int m0   = blockIdx.y * 128;
    const int n0   = blockIdx.x * 128;
    const int proj = n0 >> 10;

    if (proj != 0) {
        int len = lengths[m0 >> 9];
        if ((m0 & 511) >= ((len + 63) & ~63)) return;
    }

    const float* bias = (proj == 0) ? bq : (proj == 1) ? bk : bv;
    __half* Co = (proj == 0) ? qo : (proj == 1) ? ko : vo;
    const float sc = (proj == 0) ? QSCALE : 1.0f;

    uint32_t sb = smem_u32(smem);
    float acc[4][4][4];
#pragma unroll
    for (int i = 0; i < 4; i++)
#pragma unroll
        for (int j = 0; j < 4; j++)
#pragma unroll
            for (int k = 0; k < 4; k++) acc[i][j][k] = 0.f;

    gemm_mainloop(sb, A, Bc + (size_t)n0 * D_, m0, tid, wid, lane, acc);

    const int wm = (wid >> 2) * 64;
    const int wn = (wid & 3) * 32;
    const int er = lane >> 2;
    const int ec = (lane & 3) * 2;
#pragma unroll
    for (int mt = 0; mt < 4; mt++) {
#pragma unroll
        for (int nt = 0; nt < 4; nt++) {
            int row = m0 + wm + mt * 16 + er;
            int lc  = (n0 & 1023) + wn + nt * 8 + ec;
            float b0 = bias[lc], b1 = bias[lc + 1];
            int bb = row >> 9, ss = row & 511, hh = lc >> 6, dd = lc & 63;
            size_t base = (((size_t)bb * H_ + hh) * S_ + ss) * DH_ + dd;
            *(__half2*)(Co + base) =
                __floats2half2_rn((acc[mt][nt][0] + b0) * sc, (acc[mt][nt][1] + b1) * sc);
            *(__half2*)(Co + base + 8 * DH_) =
                __floats2half2_rn((acc[mt][nt][2] + b0) * sc, (acc[mt][nt][3] + b1) * sc);
        }
    }
}

// ---------------------------------------------------------------------------
// Output projection GEMM: out = A @ Wo^T + bo (fp32 row-major), grid (8, 64)
// ---------------------------------------------------------------------------
__global__ __launch_bounds__(256, 2) void gemm_out(
    const __half* __restrict__ A, const __half* __restrict__ Bc,
    const float* __restrict__ bias, float* __restrict__ C)
{
    extern __shared__ __align__(1024) char smem[];
    const int tid  = threadIdx.x;
    const int wid  = tid >> 5, lane = tid & 31;
    const int m0   = blockIdx.y * 128;
    const int n0   = blockIdx.x * 128;

    uint32_t sb = smem_u32(smem);
    float acc[4][4][4];
#pragma unroll
    for (int i = 0; i < 4; i++)
#pragma unroll
        for (int j = 0; j < 4; j++)
#pragma unroll
            for (int k = 0; k < 4; k++) acc[i][j][k] = 0.f;

    gemm_mainloop(sb, A, Bc + (size_t)n0 * D_, m0, tid, wid, lane, acc);

    const int wm = (wid >> 2) * 64;
    const int wn = (wid & 3) * 32;
    const int er = lane >> 2;
    const int ec = (lane & 3) * 2;
#pragma unroll
    for (int mt = 0; mt < 4; mt++) {
#pragma unroll
        for (int nt = 0; nt < 4; nt++) {
            int row = m0 + wm + mt * 16 + er;
            int col = n0 + wn + nt * 8 + ec;
            float b0 = bias[col], b1 = bias[col + 1];
            float2 p0 = make_float2(acc[mt][nt][0] + b0, acc[mt][nt][1] + b1);
            float2 p1 = make_float2(acc[mt][nt][2] + b0, acc[mt][nt][3] + b1);
            *(float2*)(C + (size_t)row * D_ + col) = p0;
            *(float2*)(C + (size_t)(row + 8) * D_ + col) = p1;
        }
    }
}

// ---------------------------------------------------------------------------
// HMMA flash attention, 64 q-rows per CTA (128 threads, 4 warps x 16 rows).
// grid (8, H, B) = 2048 CTAs -> finer work granularity (len-dependent CTA
// cost balances better) + 4 CTAs/SM (smaller barrier groups).
// fp16 operands, fp32 accum, exp2-domain softmax; deferred l reduction.
// ---------------------------------------------------------------------------
#define AQ   0
#define AST  8192
#define AK   0
#define AV   8192
#define AST_BYTES 16384
#define ATTN_SMEM (8192 + 2 * AST_BYTES)   // 40960

__global__ __launch_bounds__(128, 4) void attn_mma(
    const __half* __restrict__ Q_, const __half* __restrict__ K_,
    const __half* __restrict__ V_, const int* __restrict__ lengths,
    __half* __restrict__ O_)
{
    extern __shared__ __align__(1024) char smem[];
    const int tid = threadIdx.x, wid = tid >> 5, lane = tid & 31;
    const int b = blockIdx.z, h = blockIdx.y, q0 = blockIdx.x * 64;
    const int len = lengths[b];
    uint32_t sb = smem_u32(smem);
    const size_t bh_off = ((size_t)b * H_ + h) * (S_ * DH_);

    // Q tile load (64 rows x 128B = 512 x 16B)
#pragma unroll
    for (int i = 0; i < 4; i++) {
        int idx = tid + i * 128;
        int r = idx >> 3, c = idx & 7;
        cp16(sb + AQ + SMEM_SWZ(r * 128 + c * 16), Q_ + bh_off + (size_t)(q0 + r) * DH_ + c * 8);
    }
    CP_COMMIT();

    const int jend = (len + 63) & ~63;
    const int ntile = jend >> 6;

    // prefetch KV tile 0 -> stage 0  (64 rows x 8 chunks x 2 arrays)
    {
        uint32_t so = sb + AST;
#pragma unroll
        for (int i = 0; i < 4; i++) {
            int idx = tid + i * 128;
            int r = idx >> 3, c = idx & 7;
            size_t g = bh_off + (size_t)r * DH_ + c * 8;
            uint32_t sw = SMEM_SWZ(r * 128 + c * 16);
            cp16(so + AK + sw, K_ + g);
            cp16(so + AV + sw, V_ + g);
        }
        CP_COMMIT();
    }

    CP_WAIT1();
    __syncthreads();

    const int a_row = wid * 16 + (lane & 15);
    const int a_co = (lane >> 4) * 16;
    uint32_t qh[4][4];
#pragma unroll
    for (int s = 0; s < 4; s++) {
        uint32_t off = SMEM_SWZ(a_row * 128 + s * 32 + a_co);
        ldsm4(qh[s], sb + AQ + off);
    }

    float oa[8][4];
#pragma unroll
    for (int i = 0; i < 8; i++)
#pragma unroll
        for (int j = 0; j < 4; j++) oa[i][j] = 0.f;
    float m0 = -1e30f, m1 = -1e30f, l0 = 0.f, l1 = 0.f;

    const int krow = ((lane >> 4) << 3) + (lane & 7);
    const int kco  = ((lane >> 3) & 1) * 16;
    const int vrow = lane & 15;
    const int vco  = (lane >> 4) * 16;

#pragma unroll 1
    for (int t = 0; t < ntile; t++) {
        CP_WAIT0();
        __syncthreads();
        if (t + 1 < ntile) {
            uint32_t so = sb + AST + ((t + 1) & 1) * AST_BYTES;
            int j0n = (t + 1) * 64;
#pragma unroll
            for (int i = 0; i < 4; i++) {
                int idx = tid + i * 128;
                int r = idx >> 3, c = idx & 7;
                size_t g = bh_off + (size_t)(j0n + r) * DH_ + c * 8;
                uint32_t sw = SMEM_SWZ(r * 128 + c * 16);
                cp16(so + AK + sw, K_ + g);
                cp16(so + AV + sw, V_ + g);
            }
            CP_COMMIT();
        }

        const uint32_t so = sb + AST + (t & 1) * AST_BYTES;
        const int j0 = t * 64;

        // ---- S = Q @ K^T (log2 domain via Q pre-scale) ----
        float S[8][4];
#pragma unroll
        for (int i = 0; i < 8; i++)
#pragma unroll
            for (int j = 0; j < 4; j++) S[i][j] = 0.f;
#pragma unroll
        for (int s = 0; s < 4; s++) {
            uint32_t kh4[4][4];
#pragma unroll
            for (int g = 0; g < 4; g++) {
                uint32_t off = SMEM_SWZ((g * 16 + krow) * 128 + s * 32 + kco);
                ldsm4(kh4[g], so + AK + off);
            }
#pragma unroll
            for (int g = 0; g < 4; g++) {
                mma16816(S[2 * g],     qh[s], kh4[g]);
                mma16816(S[2 * g + 1], qh[s], kh4[g] + 2);
            }
        }

        // ---- mask (partial tiles only) ----
        if (j0 + 64 > len) {
            int kb0 = j0 + 2 * (lane & 3);
#pragma unroll
            for (int j = 0; j < 8; j++) {
#pragma unroll
                for (int e = 0; e < 4; e++) {
                    int kk = kb0 + 8 * j + (e & 1);
                    if (kk >= len) S[j][e] = -1e9f;
                }
            }
        }

        // ---- online softmax (base-2) ----
        float mx0 = -1e30f, mx1 = -1e30f;
#pragma unroll
        for (int j = 0; j < 8; j++) {
            mx0 = fmaxf(mx0, fmaxf(S[j][0], S[j][1]));
            mx1 = fmaxf(mx1, fmaxf(S[j][2], S[j][3]));
        }
        mx0 = fmaxf(mx0, __shfl_xor_sync(0xffffffffu, mx0, 1));
        mx0 = fmaxf(mx0, __shfl_xor_sync(0xffffffffu, mx0, 2));
        mx1 = fmaxf(mx1, __shfl_xor_sync(0xffffffffu, mx1, 1));
        mx1 = fmaxf(mx1, __shfl_xor_sync(0xffffffffu, mx1, 2));
        float mn0 = fmaxf(m0, mx0), mn1 = fmaxf(m1, mx1);
        float f0 = ex2(m0 - mn0), f1 = ex2(m1 - mn1);
        l0 *= f0; l1 *= f1;
#pragma unroll
        for (int i = 0; i < 8; i++) {
            oa[i][0] *= f0; oa[i][1] *= f0; oa[i][2] *= f1; oa[i][3] *= f1;
        }
#pragma unroll
        for (int j = 0; j < 8; j++) {
            S[j][0] = ex2(S[j][0] - mn0);
            S[j][1] = ex2(S[j][1] - mn0);
            S[j][2] = ex2(S[j][2] - mn1);
            S[j][3] = ex2(S[j][3] - mn1);
            l0 += S[j][0] + S[j][1];
            l1 += S[j][2] + S[j][3];
        }
        m0 = mn0; m1 = mn1;

        // ---- O += P @ V ----
#pragma unroll
        for (int s = 0; s < 4; s++) {
            uint32_t pah[4];
#pragma unroll
            for (int half = 0; half < 2; half++) {
                const float* Sf = S[2 * s + half];
                __half2 hp0 = __floats2half2_rn(Sf[0], Sf[1]);
                __half2 hp1 = __floats2half2_rn(Sf[2], Sf[3]);
                pah[2 * half]     = *(uint32_t*)&hp0;
                pah[2 * half + 1] = *(uint32_t*)&hp1;
            }
            uint32_t vh4[4][4];
#pragma unroll
            for (int g = 0; g < 4; g++) {
                uint32_t off = SMEM_SWZ((s * 16 + vrow) * 128 + g * 32 + vco);
                ldsm4t(vh4[g], so + AV + off);
            }
#pragma unroll
            for (int g = 0; g < 4; g++) {
                mma16816(oa[2 * g],     pah, vh4[g]);
                mma16816(oa[2 * g + 1], pah, vh4[g] + 2);
            }
        }
    }

    // ---- epilogue: quad-reduce l, normalize, write fp16 row-major [M][D] ----
    l0 += __shfl_xor_sync(0xffffffffu, l0, 1);
    l0 += __shfl_xor_sync(0xffffffffu, l0, 2);
    l1 += __shfl_xor_sync(0xffffffffu, l1, 1);
    l1 += __shfl_xor_sync(0xffffffffu, l1, 2);
    float il0 = 1.f / l0, il1 = 1.f / l1;
    int qrow = q0 + wid * 16 + (lane >> 2);
    size_t base0 = ((size_t)b * S_ + qrow) * D_ + h * DH_ + 2 * (lane & 3);
    size_t base1 = base0 + (size_t)8 * D_;
#pragma unroll
    for (int nf = 0; nf < 8; nf++) {
        *(__half2*)(O_ + base0 + 8 * nf) = __floats2half2_rn(oa[nf][0] * il0, oa[nf][1] * il0);
        *(__half2*)(O_ + base1 + 8 * nf) = __floats2half2_rn(oa[nf][2] * il1, oa[nf][3] * il1);
    }
}

// ---------------------------------------------------------------------------
// Combined prep: z 0..3 = weight transpose, z 4..11 = v fp32->fp16.
// grid (32,32,12), block (32,8).
// ---------------------------------------------------------------------------
__global__ __launch_bounds__(256) void prep_kernel(
    const float* __restrict__ W0, const float* __restrict__ W1,
    const float* __restrict__ W2, const float* __restrict__ W3,
    __half* __restrict__ T_,
    const float4* __restrict__ x, __half2* __restrict__ xo)
{
    const int z = blockIdx.z;
    if (z < 4) {
        __shared__ float t[32][33];
        const float* W = (z == 0) ? W0 : (z == 1) ? W1 : (z == 2) ? W2 : W3;
        const int n0 = blockIdx.x * 32, k0 = blockIdx.y * 32;
        const int tx = threadIdx.x, ty = threadIdx.y;
#pragma unroll
        for (int i = 0; i < 4; i++)
            t[ty + i * 8][tx] = W[(size_t)(k0 + ty + i * 8) * D_ + n0 + tx];
        __syncthreads();
#pragma unroll
        for (int i = 0; i < 4; i++) {
            int n = z * D_ + n0 + ty + i * 8;
            T_[(size_t)n * D_ + k0 + tx] = __float2half_rn(t[tx][ty + i * 8]);
        }
    } else {
        int tid = threadIdx.y * 32 + threadIdx.x;
        int blk = (z - 4) * 1024 + blockIdx.y * 32 + blockIdx.x;
        int i = blk * 256 + tid;
        float4 v = x[i];
        xo[2 * i]     = __floats2half2_rn(v.x, v.y);
        xo[2 * i + 1] = __floats2half2_rn(v.z, v.w);
    }
}

// ---------------------------------------------------------------------------
// Launch
// ---------------------------------------------------------------------------
extern "C" void kernel_launch(void* const* d_in, const int* in_sizes, int n_in,
                              void* d_out, int out_size)
{
    (void)in_sizes; (void)n_in; (void)out_size;
    const float* v       = (const float*)d_in[0];
    const int*   lengths = (const int*)  d_in[1];
    const float* Wq      = (const float*)d_in[2];
    const float* bq      = (const float*)d_in[3];
    const float* Wk      = (const float*)d_in[4];
    const float* bk      = (const float*)d_in[5];
    const float* Wv      = (const float*)d_in[6];
    const float* bv      = (const float*)d_in[7];
    const float* Wo      = (const float*)d_in[8];
    const float* bo      = (const float*)d_in[9];
    float* out = (float*)d_out;

    __half *xb, *wb, *qb, *kb, *vb;
    cudaGetSymbolAddress((void**)&xb, g_X);
    cudaGetSymbolAddress((void**)&wb, g_B);
    cudaGetSymbolAddress((void**)&qb, g_Q);
    cudaGetSymbolAddress((void**)&kb, g_K);
    cudaGetSymbolAddress((void**)&vb, g_V);

    cudaFuncSetAttribute(gemm_qkv, cudaFuncAttributeMaxDynamicSharedMemorySize, GEMM_SMEM);
    cudaFuncSetAttribute(gemm_out, cudaFuncAttributeMaxDynamicSharedMemorySize, GEMM_SMEM);
    cudaFuncSetAttribute(attn_mma, cudaFuncAttributeMaxDynamicSharedMemorySize, ATTN_SMEM);

    dim3 gprep(32, 32, 12), bprep(32, 8);
    prep_kernel<<<gprep, bprep>>>(Wq, Wk, Wv, Wo, wb, (const float4*)v, (__half2*)xb);

    dim3 gqkv(3 * D_ / 128, M_ / 128);   // (24, 64)
    gemm_qkv<<<gqkv, 256, GEMM_SMEM>>>(xb, wb, bq, bk, bv, qb, kb, vb, lengths);

    dim3 ga(S_ / 64, H_, B_);            // (8, 16, 16) = 2048 CTAs
    attn_mma<<<ga, 128, ATTN_SMEM>>>(qb, kb, vb, lengths, xb);

    dim3 go(D_ / 128, M_ / 128);         // (8, 64)
    gemm_out<<<go, 256, GEMM_SMEM>>>(xb, wb + (size_t)3 * D_ * D_, bo, out);
}